// round 4
// baseline (speedup 1.0000x reference)
#include <cuda_runtime.h>
#include <cstdint>

#define LDIM 128
#define CDIM 128
#define BDIM 4
#define NST  64

// Padded SMEM plane: 4 zero pad rows on top, 4 zero pad cols on left,
// row stride 133 (odd -> conflict-free for both row- and column-strided access)
#define PW 133
#define PH 132
#define PLANE (PH * PW)

// Scratch: conv output (B,C,L,L) complex, 64 MiB
__device__ float2 g_scratch[BDIM * CDIM * LDIM * LDIM];
// SSM kernels k0/k1: [which][c][l]
__device__ float2 g_k[2][CDIM][LDIM];

// ---------------------------------------------------------------------------
// Kernel 1: build k0, k1.  k[c,l] = sum_n (C*B)[c,n] * exp(l * dt[c] * A[c,n])
// ---------------------------------------------------------------------------
__global__ void k_kernel(const float* __restrict__ log_A_real,
                         const float* __restrict__ A_imag,
                         const float* __restrict__ Bp_re, const float* __restrict__ Bp_im,
                         const float* __restrict__ Cp_re, const float* __restrict__ Cp_im,
                         const float* __restrict__ log_dt)
{
    int idx = blockIdx.x * blockDim.x + threadIdx.x;
    if (idx >= 2 * CDIM * LDIM) return;
    int which = idx >> 14;          // 0..1
    int c     = (idx >> 7) & 127;   // channel
    int l     = idx & 127;          // position

    float dt = expf(log_dt[which * CDIM + c]);
    float fl = (float)l;
    float sr = 0.f, si = 0.f;
    int base = (which * CDIM + c) * NST;
    for (int n = 0; n < NST; ++n) {
        float Are = -expf(log_A_real[base + n]);
        float Aim = A_imag[which * NST + n];
        float br = Bp_re[base + n], bi = Bp_im[base + n];
        float cr = Cp_re[base + n], ci = Cp_im[base + n];
        float wr = cr * br - ci * bi;     // (C*B) elementwise complex
        float wi = cr * bi + ci * br;
        float mag = expf(fl * dt * Are);
        float ph  = fl * dt * Aim;
        float sp, cp;
        sincosf(ph, &sp, &cp);
        sr += mag * (wr * cp - wi * sp);
        si += mag * (wr * sp + wi * cp);
    }
    g_k[which][c][l] = make_float2(sr, si);
}

// ---------------------------------------------------------------------------
// Kernel 2: per-(b,c) separable causal conv, fully in SMEM.
//   pass1: along last dim (y) with k1, in-place via high->low sweeps
//   pass2: along x with k0, writes to global scratch
// 256 threads, 1 CTA per (b,c).
// ---------------------------------------------------------------------------
__global__ __launch_bounds__(256) void conv_kernel(const float* __restrict__ u_re,
                                                   const float* __restrict__ u_im)
{
    extern __shared__ float sm[];
    float* ur = sm;           // [PH][PW]
    float* ui = sm + PLANE;   // [PH][PW]
    __shared__ float k0r[LDIM], k0i[LDIM], k1r[LDIM], k1i[LDIM];

    const int bc = blockIdx.x;            // b*128 + c
    const int c  = bc & 127;
    const int t  = threadIdx.x;

    // load kernels
    for (int i = t; i < LDIM; i += 256) {
        float2 v0 = g_k[0][c][i]; k0r[i] = v0.x; k0i[i] = v0.y;
        float2 v1 = g_k[1][c][i]; k1r[i] = v1.x; k1i[i] = v1.y;
    }
    // zero padded planes
    for (int i = t; i < 2 * PLANE; i += 256) sm[i] = 0.f;
    __syncthreads();
    // load u tile (coalesced)
    const size_t ubase = (size_t)bc * (LDIM * LDIM);
    for (int i = t; i < LDIM * LDIM; i += 256) {
        int r = i >> 7, j = i & 127;
        int p = (4 + r) * PW + 4 + j;
        ur[p] = u_re[ubase + i];
        ui[p] = u_im[ubase + i];
    }
    __syncthreads();

    const int lane128 = t & 127;
    const int which   = t >> 7;

    // ---------------- pass 1: rows, kernel k1, in-place ----------------
    {
        const int rowbase = (4 + lane128) * PW;
        for (int s = 15; s >= 0; --s) {
            const int j0 = 4 * (2 * s + which);
            const int p  = rowbase + 4 + j0;
            float a0r = 0.f, a0i = 0.f, a1r = 0.f, a1i = 0.f;
            float a2r = 0.f, a2i = 0.f, a3r = 0.f, a3i = 0.f;
            float v0r = ur[p],     v0i = ui[p];
            float v1r = ur[p + 1], v1i = ui[p + 1];
            float v2r = ur[p + 2], v2i = ui[p + 2];
            float v3r = ur[p + 3], v3i = ui[p + 3];
            const int imax = j0 + 3;
            for (int i = 0; i <= imax; ++i) {
                float kr = k1r[i], ki = k1i[i];
                a0r += kr * v0r - ki * v0i;  a0i += kr * v0i + ki * v0r;
                a1r += kr * v1r - ki * v1i;  a1i += kr * v1i + ki * v1r;
                a2r += kr * v2r - ki * v2i;  a2i += kr * v2i + ki * v2r;
                a3r += kr * v3r - ki * v3i;  a3i += kr * v3i + ki * v3r;
                v3r = v2r; v3i = v2i; v2r = v1r; v2i = v1i; v1r = v0r; v1i = v0i;
                int q = rowbase + 4 + j0 - (i + 1);   // left pad -> zeros, no guards
                v0r = ur[q]; v0i = ui[q];
            }
            __syncthreads();
            ur[p] = a0r;     ui[p] = a0i;
            ur[p + 1] = a1r; ui[p + 1] = a1i;
            ur[p + 2] = a2r; ui[p + 2] = a2i;
            ur[p + 3] = a3r; ui[p + 3] = a3i;
            __syncthreads();
        }
    }

    // ---------------- pass 2: columns, kernel k0, to global ----------------
    {
        const int y = lane128;
        for (int m2 = 0; m2 < 16; ++m2) {
            const int x0 = 4 * (2 * m2 + which);
            const int p  = (4 + x0) * PW + 4 + y;
            float a0r = 0.f, a0i = 0.f, a1r = 0.f, a1i = 0.f;
            float a2r = 0.f, a2i = 0.f, a3r = 0.f, a3i = 0.f;
            float v0r = ur[p],          v0i = ui[p];
            float v1r = ur[p + PW],     v1i = ui[p + PW];
            float v2r = ur[p + 2 * PW], v2i = ui[p + 2 * PW];
            float v3r = ur[p + 3 * PW], v3i = ui[p + 3 * PW];
            const int imax = x0 + 3;
            for (int i = 0; i <= imax; ++i) {
                float kr = k0r[i], ki = k0i[i];
                a0r += kr * v0r - ki * v0i;  a0i += kr * v0i + ki * v0r;
                a1r += kr * v1r - ki * v1i;  a1i += kr * v1i + ki * v1r;
                a2r += kr * v2r - ki * v2i;  a2i += kr * v2i + ki * v2r;
                a3r += kr * v3r - ki * v3i;  a3i += kr * v3i + ki * v3r;
                v3r = v2r; v3i = v2i; v2r = v1r; v2i = v1i; v1r = v0r; v1i = v0i;
                int q = p - (i + 1) * PW;             // top pad -> zeros
                v0r = ur[q]; v0i = ui[q];
            }
            const size_t obase = (size_t)bc * (LDIM * LDIM) + (size_t)x0 * LDIM + y;
            g_scratch[obase]             = make_float2(a0r, a0i);
            g_scratch[obase + LDIM]      = make_float2(a1r, a1i);
            g_scratch[obase + 2 * LDIM]  = make_float2(a2r, a2i);
            g_scratch[obase + 3 * LDIM]  = make_float2(a3r, a3i);
        }
    }
}

// ---------------------------------------------------------------------------
// Kernel 3: complex channel mix.  out[b,d,p] = sum_c W[d,c] * s[b,c,p]
// Tiled complex GEMM: M=128 (d), N=128 pixels/CTA, K=128 (c), Kc=16 chunks.
// grid = B * (16384/128) = 512 CTAs, 256 threads (16x16), 8x8 complex acc.
// MODE 0: out is interleaved (re,im) pairs -> 16777216 floats (64 MB)
// MODE 1: out is REAL PART ONLY (float32)  ->  8388608 floats (32 MB)
// ---------------------------------------------------------------------------
__global__ __launch_bounds__(256) void mix_kernel(const float* __restrict__ W_re,
                                                  const float* __restrict__ W_im,
                                                  float* __restrict__ out,
                                                  int mode)
{
    __shared__ float2 Wc[16][128];   // [ci][d]
    __shared__ float2 Sc[16][128];   // [ci][p]

    const int bidx = blockIdx.x;
    const int b  = bidx >> 7;
    const int p0 = (bidx & 127) * 128;
    const int tid = threadIdx.x;
    const int tx = tid & 15;   // pixel group
    const int ty = tid >> 4;   // d group

    float accr[8][8], acci[8][8];
#pragma unroll
    for (int j = 0; j < 8; ++j)
#pragma unroll
        for (int jj = 0; jj < 8; ++jj) { accr[j][jj] = 0.f; acci[j][jj] = 0.f; }

    for (int cc = 0; cc < CDIM; cc += 16) {
        __syncthreads();
        // load W chunk transposed: Wc[ci][d]
        for (int idx = tid; idx < 16 * 128; idx += 256) {
            int d = idx >> 4, ci = idx & 15;
            int g = d * CDIM + cc + ci;
            Wc[ci][d] = make_float2(W_re[g], W_im[g]);
        }
        // load s chunk: Sc[ci][p]
        for (int idx = tid; idx < 16 * 128; idx += 256) {
            int ci = idx >> 7, p = idx & 127;
            Sc[ci][p] = g_scratch[((size_t)(b * CDIM + cc + ci) << 14) + p0 + p];
        }
        __syncthreads();
#pragma unroll
        for (int ci = 0; ci < 16; ++ci) {
            float2 w[8], s[8];
#pragma unroll
            for (int j = 0; j < 8; ++j)  w[j] = Wc[ci][ty + 16 * j];
#pragma unroll
            for (int jj = 0; jj < 8; ++jj) s[jj] = Sc[ci][tx + 16 * jj];
#pragma unroll
            for (int j = 0; j < 8; ++j)
#pragma unroll
                for (int jj = 0; jj < 8; ++jj) {
                    accr[j][jj] += w[j].x * s[jj].x - w[j].y * s[jj].y;
                    acci[j][jj] += w[j].x * s[jj].y + w[j].y * s[jj].x;
                }
        }
    }

    if (mode == 0) {
        float2* out2 = (float2*)out;       // 8388608 float2 slots (64 MB)
#pragma unroll
        for (int j = 0; j < 8; ++j) {
            int d = ty + 16 * j;
            size_t rowb = ((size_t)(b * CDIM + d) << 14) + p0;
#pragma unroll
            for (int jj = 0; jj < 8; ++jj)
                out2[rowb + tx + 16 * jj] = make_float2(accr[j][jj], acci[j][jj]);
        }
    } else {
        // real part only: max index 8388607 -> fits a 32 MB float buffer
#pragma unroll
        for (int j = 0; j < 8; ++j) {
            int d = ty + 16 * j;
            size_t rowb = ((size_t)(b * CDIM + d) << 14) + p0;
#pragma unroll
            for (int jj = 0; jj < 8; ++jj)
                out[rowb + tx + 16 * jj] = accr[j][jj];
        }
    }
}

// ---------------------------------------------------------------------------
// Host: bind input pointers BY SIZE SIGNATURE (memory-safe against any order).
// ---------------------------------------------------------------------------
extern "C" void kernel_launch(void* const* d_in, const int* in_sizes, int n_in,
                              void* d_out, int out_size)
{
    const float* big[2]   = {nullptr, nullptr};
    const float* mid[16];                    // 16384-sized, encounter order
    const float* a_imag_p = nullptr;
    const float* log_dt_p = nullptr;
    int nbig = 0, nmid = 0, a_pos = -1;

    for (int i = 0; i < n_in; ++i) {
        const float* p = (const float*)d_in[i];
        int sz = in_sizes[i];
        if (sz == BDIM * CDIM * LDIM * LDIM) { if (nbig < 2) big[nbig++] = p; }
        else if (sz == 2 * NST)              { a_imag_p = p; a_pos = i; }
        else if (sz == 2 * CDIM)             { log_dt_p = p; }
        else if (sz == CDIM * CDIM && nmid < 16) { mid[nmid++] = p; }
    }
    if (nbig != 2 || !a_imag_p || !log_dt_p || nmid < 7) return;  // can't bind safely

    const float *u_re = big[0], *u_im = big[1];
    const float *log_A_real, *Bp_re, *Bp_im, *Cp_re, *Cp_im, *W_re, *W_im;
    if (a_pos == 0) {
        // ASCII-sorted order: A_imag,Bp_im,Bp_re,Cp_im,Cp_re,W_im,W_re,log_A_real,log_dt,u_im,u_re
        Bp_im = mid[0]; Bp_re = mid[1]; Cp_im = mid[2]; Cp_re = mid[3];
        W_im  = mid[4]; W_re  = mid[5]; log_A_real = mid[6];
        u_im = big[0]; u_re = big[1];   // u_im precedes u_re in ASCII order
    } else {
        // dict / signature order
        log_A_real = mid[0]; Bp_re = mid[1]; Bp_im = mid[2];
        Cp_re = mid[3]; Cp_im = mid[4]; W_re = mid[5]; W_im = mid[6];
    }

    // Output layout: >= 16.7M elements -> interleaved complex view;
    // otherwise (e.g. 8388608 float32) -> real part only.
    const int mode = (out_size >= 2 * BDIM * CDIM * LDIM * LDIM) ? 0 : 1;

    // 1) SSM kernels k0 (along x) and k1 (along y)
    k_kernel<<<128, 256>>>(log_A_real, a_imag_p, Bp_re, Bp_im, Cp_re, Cp_im, log_dt_p);

    // 2) separable causal conv, one CTA per (b, c)
    const int conv_smem = 2 * PLANE * (int)sizeof(float);  // 140448 B
    cudaFuncSetAttribute(conv_kernel, cudaFuncAttributeMaxDynamicSharedMemorySize, conv_smem);
    conv_kernel<<<BDIM * CDIM, 256, conv_smem>>>(u_re, u_im);

    // 3) complex channel mix
    mix_kernel<<<BDIM * 128, 256>>>(W_re, W_im, (float*)d_out, mode);
}

// round 5
// speedup vs baseline: 1.3508x; 1.3508x over previous
#include <cuda_runtime.h>
#include <cstdint>

#define LDIM 128
#define CDIM 128
#define BDIM 4
#define NST  64

// Padded SMEM plane (float2 elements): 4 pad rows on top, 4 pad cols left,
// row stride 133 float2.
#define PW 133
#define PH 132
#define PLANE (PH * PW)

__device__ float2 g_scratch[BDIM * CDIM * LDIM * LDIM];   // conv output, 64 MiB
__device__ float2 g_k[2][CDIM][LDIM];                     // SSM kernels

typedef unsigned long long u64;

__device__ __forceinline__ u64 pk2(float lo, float hi) {
    u64 r; asm("mov.b64 %0, {%1,%2};" : "=l"(r) : "f"(lo), "f"(hi)); return r;
}
__device__ __forceinline__ void upk2(u64 v, float& lo, float& hi) {
    asm("mov.b64 {%0,%1}, %2;" : "=f"(lo), "=f"(hi) : "l"(v));
}
#define FMA2(d, a, b) asm("fma.rn.f32x2 %0, %1, %2, %0;" : "+l"(d) : "l"(a), "l"(b))

// ---------------------------------------------------------------------------
// Kernel 1: build k0, k1.
// ---------------------------------------------------------------------------
__global__ void k_kernel(const float* __restrict__ log_A_real,
                         const float* __restrict__ A_imag,
                         const float* __restrict__ Bp_re, const float* __restrict__ Bp_im,
                         const float* __restrict__ Cp_re, const float* __restrict__ Cp_im,
                         const float* __restrict__ log_dt)
{
    int idx = blockIdx.x * blockDim.x + threadIdx.x;
    if (idx >= 2 * CDIM * LDIM) return;
    int which = idx >> 14;
    int c     = (idx >> 7) & 127;
    int l     = idx & 127;

    float dt = expf(log_dt[which * CDIM + c]);
    float fl = (float)l;
    float sr = 0.f, si = 0.f;
    int base = (which * CDIM + c) * NST;
    for (int n = 0; n < NST; ++n) {
        float Are = -expf(log_A_real[base + n]);
        float Aim = A_imag[which * NST + n];
        float br = Bp_re[base + n], bi = Bp_im[base + n];
        float cr = Cp_re[base + n], ci = Cp_im[base + n];
        float wr = cr * br - ci * bi;
        float wi = cr * bi + ci * br;
        float mag = expf(fl * dt * Are);
        float ph  = fl * dt * Aim;
        float sp, cp;
        sincosf(ph, &sp, &cp);
        sr += mag * (wr * cp - wi * sp);
        si += mag * (wr * sp + wi * cp);
    }
    g_k[which][c][l] = make_float2(sr, si);
}

// ---------------------------------------------------------------------------
// Kernel 2: per-(b,c) separable causal conv, packed f32x2 math.
// Complex MAC trick: A += (kr,kr)*(vr,vi); B += (ki,ki)*(vr,vi);
//                    out = (A.lo - B.hi, A.hi + B.lo)
// ---------------------------------------------------------------------------
__global__ __launch_bounds__(256) void conv_kernel(const float* __restrict__ u_re,
                                                   const float* __restrict__ u_im)
{
    extern __shared__ float2 pl[];                 // [PH][PW] interleaved (re,im)
    __shared__ u64 k0p[LDIM], k0b[LDIM], k1p[LDIM], k1b[LDIM];

    const int bc = blockIdx.x;
    const int c  = bc & 127;
    const int t  = threadIdx.x;

    for (int i = t; i < LDIM; i += 256) {
        float2 v0 = g_k[0][c][i]; k0p[i] = pk2(v0.x, v0.x); k0b[i] = pk2(v0.y, v0.y);
        float2 v1 = g_k[1][c][i]; k1p[i] = pk2(v1.x, v1.x); k1b[i] = pk2(v1.y, v1.y);
    }
    for (int i = t; i < PLANE; i += 256) pl[i] = make_float2(0.f, 0.f);
    __syncthreads();
    const size_t ubase = (size_t)bc * (LDIM * LDIM);
    for (int i = t; i < LDIM * LDIM; i += 256) {
        int r = i >> 7, j = i & 127;
        pl[(4 + r) * PW + 4 + j] = make_float2(u_re[ubase + i], u_im[ubase + i]);
    }
    __syncthreads();

    const int lane128 = t & 127;
    const int which   = t >> 7;
    const u64* pp = (const u64*)pl;

    // ---------------- pass 1: rows, kernel k1, in-place ----------------
    {
        const int rowbase = (4 + lane128) * PW;
        for (int s = 15; s >= 0; --s) {
            const int j0 = 4 * (2 * s + which);
            const int P  = rowbase + 4 + j0;
            u64 A0 = 0, B0 = 0, A1 = 0, B1 = 0, A2 = 0, B2 = 0, A3 = 0, B3 = 0;
            u64 v0 = pp[P], v1 = pp[P + 1], v2 = pp[P + 2], v3 = pp[P + 3];
            const int n = j0 + 4;                  // always divisible by 4
#pragma unroll 4
            for (int i = 0; i < n; ++i) {
                u64 kp = k1p[i], kb = k1b[i];
                FMA2(A0, kp, v0); FMA2(B0, kb, v0);
                FMA2(A1, kp, v1); FMA2(B1, kb, v1);
                FMA2(A2, kp, v2); FMA2(B2, kb, v2);
                FMA2(A3, kp, v3); FMA2(B3, kb, v3);
                v3 = v2; v2 = v1; v1 = v0; v0 = pp[P - 1 - i];
            }
            __syncthreads();                       // step-s reads done before writes
            float ar, ai2, br2, bi2;
            upk2(A0, ar, ai2); upk2(B0, br2, bi2);
            pl[P]     = make_float2(ar - bi2, ai2 + br2);
            upk2(A1, ar, ai2); upk2(B1, br2, bi2);
            pl[P + 1] = make_float2(ar - bi2, ai2 + br2);
            upk2(A2, ar, ai2); upk2(B2, br2, bi2);
            pl[P + 2] = make_float2(ar - bi2, ai2 + br2);
            upk2(A3, ar, ai2); upk2(B3, br2, bi2);
            pl[P + 3] = make_float2(ar - bi2, ai2 + br2);
        }
    }
    __syncthreads();

    // ---------------- pass 2: columns, kernel k0, to global ----------------
    {
        const int y = lane128;
        for (int m2 = 0; m2 < 16; ++m2) {
            const int x0 = 4 * (2 * m2 + which);
            const int P  = (4 + x0) * PW + 4 + y;
            u64 A0 = 0, B0 = 0, A1 = 0, B1 = 0, A2 = 0, B2 = 0, A3 = 0, B3 = 0;
            u64 v0 = pp[P], v1 = pp[P + PW], v2 = pp[P + 2 * PW], v3 = pp[P + 3 * PW];
            const int n = x0 + 4;
#pragma unroll 4
            for (int i = 0; i < n; ++i) {
                u64 kp = k0p[i], kb = k0b[i];
                FMA2(A0, kp, v0); FMA2(B0, kb, v0);
                FMA2(A1, kp, v1); FMA2(B1, kb, v1);
                FMA2(A2, kp, v2); FMA2(B2, kb, v2);
                FMA2(A3, kp, v3); FMA2(B3, kb, v3);
                v3 = v2; v2 = v1; v1 = v0; v0 = pp[P - (i + 1) * PW];
            }
            const size_t obase = (size_t)bc * (LDIM * LDIM) + (size_t)x0 * LDIM + y;
            float ar, ai2, br2, bi2;
            upk2(A0, ar, ai2); upk2(B0, br2, bi2);
            g_scratch[obase]            = make_float2(ar - bi2, ai2 + br2);
            upk2(A1, ar, ai2); upk2(B1, br2, bi2);
            g_scratch[obase + LDIM]     = make_float2(ar - bi2, ai2 + br2);
            upk2(A2, ar, ai2); upk2(B2, br2, bi2);
            g_scratch[obase + 2 * LDIM] = make_float2(ar - bi2, ai2 + br2);
            upk2(A3, ar, ai2); upk2(B3, br2, bi2);
            g_scratch[obase + 3 * LDIM] = make_float2(ar - bi2, ai2 + br2);
        }
    }
}

// ---------------------------------------------------------------------------
// Kernel 3: complex channel mix, packed f32x2 along pixel pairs (p, p+64).
//   accre += (wr,wr)*(srA,srB) + (wi,wi)*(-siA,-siB)
//   accim += (wr,wr)*(siA,siB) + (wi,wi)*(srA,srB)
// SMEM layout (u64 units): Wrr[0,2048) Wii[2048,4096) Sr2[4096,5120)
//                          Si2[5120,6144) Sn2[6144,7168)   = 57344 B
// ---------------------------------------------------------------------------
__global__ __launch_bounds__(256) void mix_kernel(const float* __restrict__ W_re,
                                                  const float* __restrict__ W_im,
                                                  float* __restrict__ out,
                                                  int mode)
{
    extern __shared__ u64 sm64[];
    u64* Wrr = sm64;            // [d*16 + ci]
    u64* Wii = sm64 + 2048;
    u64* Sr2 = sm64 + 4096;     // [ci*64 + e], pair = pixels (e, e+64)
    u64* Si2 = sm64 + 5120;
    u64* Sn2 = sm64 + 6144;

    const int bidx = blockIdx.x;
    const int b  = bidx >> 7;
    const int p0 = (bidx & 127) * 128;
    const int tid = threadIdx.x;
    const int tx = tid & 15;
    const int ty = tid >> 4;

    u64 accre[8][4], accim[8][4];
#pragma unroll
    for (int j = 0; j < 8; ++j)
#pragma unroll
        for (int m = 0; m < 4; ++m) { accre[j][m] = 0; accim[j][m] = 0; }

    for (int cc = 0; cc < CDIM; cc += 16) {
        __syncthreads();
        for (int idx = tid; idx < 2048; idx += 256) {
            int d = idx >> 4, ci = idx & 15;
            int g = d * CDIM + cc + ci;
            float wr = W_re[g], wi = W_im[g];
            Wrr[(d << 4) | ci] = pk2(wr, wr);
            Wii[(d << 4) | ci] = pk2(wi, wi);
        }
        for (int idx = tid; idx < 2048; idx += 256) {
            int ci = idx >> 7, p = idx & 127;
            float2 s = g_scratch[((size_t)(b * CDIM + cc + ci) << 14) + p0 + p];
            int e = p & 63, hi = p >> 6;
            ((float*)&Sr2[(ci << 6) + e])[hi] = s.x;
            ((float*)&Si2[(ci << 6) + e])[hi] = s.y;
            ((float*)&Sn2[(ci << 6) + e])[hi] = -s.y;
        }
        __syncthreads();
#pragma unroll
        for (int ci = 0; ci < 16; ++ci) {
            u64 sr[4], si[4], sn[4];
#pragma unroll
            for (int m = 0; m < 4; ++m) {
                int e = tx + 16 * m;
                sr[m] = Sr2[(ci << 6) + e];
                si[m] = Si2[(ci << 6) + e];
                sn[m] = Sn2[(ci << 6) + e];
            }
#pragma unroll
            for (int j = 0; j < 8; ++j) {
                u64 wr2 = Wrr[((ty + 16 * j) << 4) | ci];
                u64 wi2 = Wii[((ty + 16 * j) << 4) | ci];
#pragma unroll
                for (int m = 0; m < 4; ++m) {
                    FMA2(accre[j][m], wr2, sr[m]);
                    FMA2(accre[j][m], wi2, sn[m]);
                    FMA2(accim[j][m], wr2, si[m]);
                    FMA2(accim[j][m], wi2, sr[m]);
                }
            }
        }
    }

    if (mode == 0) {
        float2* out2 = (float2*)out;
#pragma unroll
        for (int j = 0; j < 8; ++j) {
            int d = ty + 16 * j;
            size_t rowb = ((size_t)(b * CDIM + d) << 14) + p0;
#pragma unroll
            for (int m = 0; m < 4; ++m) {
                float reA, reB, imA, imB;
                upk2(accre[j][m], reA, reB);
                upk2(accim[j][m], imA, imB);
                out2[rowb + tx + 16 * m]      = make_float2(reA, imA);
                out2[rowb + tx + 16 * m + 64] = make_float2(reB, imB);
            }
        }
    } else {
#pragma unroll
        for (int j = 0; j < 8; ++j) {
            int d = ty + 16 * j;
            size_t rowb = ((size_t)(b * CDIM + d) << 14) + p0;
#pragma unroll
            for (int m = 0; m < 4; ++m) {
                float reA, reB;
                upk2(accre[j][m], reA, reB);
                out[rowb + tx + 16 * m]      = reA;
                out[rowb + tx + 16 * m + 64] = reB;
            }
        }
    }
}

// ---------------------------------------------------------------------------
// Host: bind input pointers BY SIZE SIGNATURE (memory-safe against any order).
// ---------------------------------------------------------------------------
extern "C" void kernel_launch(void* const* d_in, const int* in_sizes, int n_in,
                              void* d_out, int out_size)
{
    const float* big[2]   = {nullptr, nullptr};
    const float* mid[16];
    const float* a_imag_p = nullptr;
    const float* log_dt_p = nullptr;
    int nbig = 0, nmid = 0, a_pos = -1;

    for (int i = 0; i < n_in; ++i) {
        const float* p = (const float*)d_in[i];
        int sz = in_sizes[i];
        if (sz == BDIM * CDIM * LDIM * LDIM) { if (nbig < 2) big[nbig++] = p; }
        else if (sz == 2 * NST)              { a_imag_p = p; a_pos = i; }
        else if (sz == 2 * CDIM)             { log_dt_p = p; }
        else if (sz == CDIM * CDIM && nmid < 16) { mid[nmid++] = p; }
    }
    if (nbig != 2 || !a_imag_p || !log_dt_p || nmid < 7) return;

    const float *u_re = big[0], *u_im = big[1];
    const float *log_A_real, *Bp_re, *Bp_im, *Cp_re, *Cp_im, *W_re, *W_im;
    if (a_pos == 0) {
        Bp_im = mid[0]; Bp_re = mid[1]; Cp_im = mid[2]; Cp_re = mid[3];
        W_im  = mid[4]; W_re  = mid[5]; log_A_real = mid[6];
        u_im = big[0]; u_re = big[1];
    } else {
        log_A_real = mid[0]; Bp_re = mid[1]; Bp_im = mid[2];
        Cp_re = mid[3]; Cp_im = mid[4]; W_re = mid[5]; W_im = mid[6];
    }

    const int mode = (out_size >= 2 * BDIM * CDIM * LDIM * LDIM) ? 0 : 1;

    k_kernel<<<128, 256>>>(log_A_real, a_imag_p, Bp_re, Bp_im, Cp_re, Cp_im, log_dt_p);

    const int conv_smem = PLANE * (int)sizeof(float2);        // 140448 B
    cudaFuncSetAttribute(conv_kernel, cudaFuncAttributeMaxDynamicSharedMemorySize, conv_smem);
    conv_kernel<<<BDIM * CDIM, 256, conv_smem>>>(u_re, u_im);

    const int mix_smem = 7168 * (int)sizeof(u64);             // 57344 B
    cudaFuncSetAttribute(mix_kernel, cudaFuncAttributeMaxDynamicSharedMemorySize, mix_smem);
    mix_kernel<<<BDIM * 128, 256, mix_smem>>>(W_re, W_im, (float*)d_out, mode);
}

// round 7
// speedup vs baseline: 1.9040x; 1.4095x over previous
#include <cuda_runtime.h>
#include <cuda_bf16.h>
#include <cstdint>

#define LDIM 128
#define CDIM 128
#define BDIM 4
#define NST  64

#define PW 133
#define PH 132
#define PLANE (PH * PW)

__device__ float2 g_scratch[BDIM * CDIM * LDIM * LDIM];   // conv output, 64 MiB
__device__ float2 g_k[2][CDIM][LDIM];                     // SSM kernels
// W split planes for HMMA path: [mat: 0=Wr_h 1=Wr_l 2=-Wi_h 3=-Wi_l][half][d*64+cl]
__device__ __nv_bfloat16 g_Wbf[4][2][8192];

typedef unsigned long long u64;

__device__ __forceinline__ u64 pk2(float lo, float hi) {
    u64 r; asm("mov.b64 %0, {%1,%2};" : "=l"(r) : "f"(lo), "f"(hi)); return r;
}
__device__ __forceinline__ void upk2(u64 v, float& lo, float& hi) {
    asm("mov.b64 {%0,%1}, %2;" : "=f"(lo), "=f"(hi) : "l"(v));
}
#define FMA2(d, a, b) asm("fma.rn.f32x2 %0, %1, %2, %0;" : "+l"(d) : "l"(a), "l"(b))

#define MMA16816(d, a, b) \
    asm volatile("mma.sync.aligned.m16n8k16.row.col.f32.bf16.bf16.f32 " \
        "{%0,%1,%2,%3}, {%4,%5,%6,%7}, {%8,%9}, {%0,%1,%2,%3};" \
        : "+f"((d)[0]), "+f"((d)[1]), "+f"((d)[2]), "+f"((d)[3]) \
        : "r"((a)[0]), "r"((a)[1]), "r"((a)[2]), "r"((a)[3]), \
          "r"((b)[0]), "r"((b)[1]))

// ---------------------------------------------------------------------------
// Kernel 1: build k0, k1.
// ---------------------------------------------------------------------------
__global__ void k_kernel(const float* __restrict__ log_A_real,
                         const float* __restrict__ A_imag,
                         const float* __restrict__ Bp_re, const float* __restrict__ Bp_im,
                         const float* __restrict__ Cp_re, const float* __restrict__ Cp_im,
                         const float* __restrict__ log_dt)
{
    int idx = blockIdx.x * blockDim.x + threadIdx.x;
    if (idx >= 2 * CDIM * LDIM) return;
    int which = idx >> 14;
    int c     = (idx >> 7) & 127;
    int l     = idx & 127;

    float dt = expf(log_dt[which * CDIM + c]);
    float fl = (float)l;
    float sr = 0.f, si = 0.f;
    int base = (which * CDIM + c) * NST;
    for (int n = 0; n < NST; ++n) {
        float Are = -expf(log_A_real[base + n]);
        float Aim = A_imag[which * NST + n];
        float br = Bp_re[base + n], bi = Bp_im[base + n];
        float cr = Cp_re[base + n], ci = Cp_im[base + n];
        float wr = cr * br - ci * bi;
        float wi = cr * bi + ci * br;
        float mag = expf(fl * dt * Are);
        float ph  = fl * dt * Aim;
        float sp, cp;
        sincosf(ph, &sp, &cp);
        sr += mag * (wr * cp - wi * sp);
        si += mag * (wr * sp + wi * cp);
    }
    g_k[which][c][l] = make_float2(sr, si);
}

// ---------------------------------------------------------------------------
// Kernel 1b: split W into bf16 hi/lo planes (Wi planes pre-negated).
// ---------------------------------------------------------------------------
__global__ void wprep_kernel(const float* __restrict__ W_re,
                             const float* __restrict__ W_im)
{
    int idx = blockIdx.x * blockDim.x + threadIdx.x;
    if (idx >= CDIM * CDIM) return;
    int d = idx >> 7, c = idx & 127;
    int half = c >> 6, cl = c & 63;
    int off = d * 64 + cl;
    float wr = W_re[idx], nwi = -W_im[idx];
    __nv_bfloat16 h;
    h = __float2bfloat16(wr);
    g_Wbf[0][half][off] = h;
    g_Wbf[1][half][off] = __float2bfloat16(wr - __bfloat162float(h));
    h = __float2bfloat16(nwi);
    g_Wbf[2][half][off] = h;
    g_Wbf[3][half][off] = __float2bfloat16(nwi - __bfloat162float(h));
}

// ---------------------------------------------------------------------------
// Kernel 2: per-(b,c) separable causal conv, packed f32x2 math. (unchanged)
// ---------------------------------------------------------------------------
__global__ __launch_bounds__(256) void conv_kernel(const float* __restrict__ u_re,
                                                   const float* __restrict__ u_im)
{
    extern __shared__ float2 pl[];
    __shared__ u64 k0p[LDIM], k0b[LDIM], k1p[LDIM], k1b[LDIM];

    const int bc = blockIdx.x;
    const int c  = bc & 127;
    const int t  = threadIdx.x;

    for (int i = t; i < LDIM; i += 256) {
        float2 v0 = g_k[0][c][i]; k0p[i] = pk2(v0.x, v0.x); k0b[i] = pk2(v0.y, v0.y);
        float2 v1 = g_k[1][c][i]; k1p[i] = pk2(v1.x, v1.x); k1b[i] = pk2(v1.y, v1.y);
    }
    for (int i = t; i < PLANE; i += 256) pl[i] = make_float2(0.f, 0.f);
    __syncthreads();
    const size_t ubase = (size_t)bc * (LDIM * LDIM);
    for (int i = t; i < LDIM * LDIM; i += 256) {
        int r = i >> 7, j = i & 127;
        pl[(4 + r) * PW + 4 + j] = make_float2(u_re[ubase + i], u_im[ubase + i]);
    }
    __syncthreads();

    const int lane128 = t & 127;
    const int which   = t >> 7;
    const u64* pp = (const u64*)pl;

    {
        const int rowbase = (4 + lane128) * PW;
        for (int s = 15; s >= 0; --s) {
            const int j0 = 4 * (2 * s + which);
            const int P  = rowbase + 4 + j0;
            u64 A0 = 0, B0 = 0, A1 = 0, B1 = 0, A2 = 0, B2 = 0, A3 = 0, B3 = 0;
            u64 v0 = pp[P], v1 = pp[P + 1], v2 = pp[P + 2], v3 = pp[P + 3];
            const int n = j0 + 4;
#pragma unroll 4
            for (int i = 0; i < n; ++i) {
                u64 kp = k1p[i], kb = k1b[i];
                FMA2(A0, kp, v0); FMA2(B0, kb, v0);
                FMA2(A1, kp, v1); FMA2(B1, kb, v1);
                FMA2(A2, kp, v2); FMA2(B2, kb, v2);
                FMA2(A3, kp, v3); FMA2(B3, kb, v3);
                v3 = v2; v2 = v1; v1 = v0; v0 = pp[P - 1 - i];
            }
            __syncthreads();
            float ar, ai2, br2, bi2;
            upk2(A0, ar, ai2); upk2(B0, br2, bi2);
            pl[P]     = make_float2(ar - bi2, ai2 + br2);
            upk2(A1, ar, ai2); upk2(B1, br2, bi2);
            pl[P + 1] = make_float2(ar - bi2, ai2 + br2);
            upk2(A2, ar, ai2); upk2(B2, br2, bi2);
            pl[P + 2] = make_float2(ar - bi2, ai2 + br2);
            upk2(A3, ar, ai2); upk2(B3, br2, bi2);
            pl[P + 3] = make_float2(ar - bi2, ai2 + br2);
        }
    }
    __syncthreads();

    {
        const int y = lane128;
        for (int m2 = 0; m2 < 16; ++m2) {
            const int x0 = 4 * (2 * m2 + which);
            const int P  = (4 + x0) * PW + 4 + y;
            u64 A0 = 0, B0 = 0, A1 = 0, B1 = 0, A2 = 0, B2 = 0, A3 = 0, B3 = 0;
            u64 v0 = pp[P], v1 = pp[P + PW], v2 = pp[P + 2 * PW], v3 = pp[P + 3 * PW];
            const int n = x0 + 4;
#pragma unroll 4
            for (int i = 0; i < n; ++i) {
                u64 kp = k0p[i], kb = k0b[i];
                FMA2(A0, kp, v0); FMA2(B0, kb, v0);
                FMA2(A1, kp, v1); FMA2(B1, kb, v1);
                FMA2(A2, kp, v2); FMA2(B2, kb, v2);
                FMA2(A3, kp, v3); FMA2(B3, kb, v3);
                v3 = v2; v2 = v1; v1 = v0; v0 = pp[P - (i + 1) * PW];
            }
            const size_t obase = (size_t)bc * (LDIM * LDIM) + (size_t)x0 * LDIM + y;
            float ar, ai2, br2, bi2;
            upk2(A0, ar, ai2); upk2(B0, br2, bi2);
            g_scratch[obase]            = make_float2(ar - bi2, ai2 + br2);
            upk2(A1, ar, ai2); upk2(B1, br2, bi2);
            g_scratch[obase + LDIM]     = make_float2(ar - bi2, ai2 + br2);
            upk2(A2, ar, ai2); upk2(B2, br2, bi2);
            g_scratch[obase + 2 * LDIM] = make_float2(ar - bi2, ai2 + br2);
            upk2(A3, ar, ai2); upk2(B3, br2, bi2);
            g_scratch[obase + 3 * LDIM] = make_float2(ar - bi2, ai2 + br2);
        }
    }
}

// ---------------------------------------------------------------------------
// Kernel 3 (mode 1, real output): mix via mma.sync bf16-split GEMM.
// CTA: M=128(d) x N=128(px) x K=128(c), K processed in 2 halves of 64.
// SMEM (b32 units): A region 4 planes x 4608 (rows d, stride 36 b32 = 72 bf16),
//                   S region 4 planes x 4608 (rows p, k contiguous).
// re = Wr*Sr + (-Wi)*Si, each product ~ hi*hi + lo*hi + hi*lo.
// ---------------------------------------------------------------------------
#define WSTR 36                 // b32 row stride
#define PLANE32 4608            // b32 per plane
#define S_OFFB (4 * PLANE32)
#define MIXMMA_SMEM (8 * PLANE32 * 4)   // 147456 bytes

__global__ __launch_bounds__(256) void mix_mma_kernel(float* __restrict__ out)
{
    extern __shared__ __align__(16) uint32_t sw[];
    const int tid  = threadIdx.x;
    const int warp = tid >> 5, lane = tid & 31;
    const int g = lane >> 2, t = lane & 3;
    const int b  = blockIdx.x >> 7;
    const int p0 = (blockIdx.x & 127) * 128;
    const int m0 = warp * 16;

    float acc[16][4];
#pragma unroll
    for (int n = 0; n < 16; ++n)
#pragma unroll
        for (int i = 0; i < 4; ++i) acc[n][i] = 0.f;

    for (int half = 0; half < 2; ++half) {
        // ---- load W planes (b32 copies with pad) ----
        {
            const uint32_t* s0 = (const uint32_t*)&g_Wbf[0][half][0];
            const uint32_t* s1 = (const uint32_t*)&g_Wbf[1][half][0];
            const uint32_t* s2 = (const uint32_t*)&g_Wbf[2][half][0];
            const uint32_t* s3 = (const uint32_t*)&g_Wbf[3][half][0];
            for (int i = tid; i < 4096; i += 256) {
                int d = i >> 5, cw = i & 31;
                int dst = d * WSTR + cw;
                sw[dst]               = s0[i];
                sw[PLANE32 + dst]     = s1[i];
                sw[2 * PLANE32 + dst] = s2[i];
                sw[3 * PLANE32 + dst] = s3[i];
            }
        }
        // ---- convert S chunk: S_T[p][cl] bf16 hi/lo for re and im ----
        {
            __nv_bfloat16* sb = (__nv_bfloat16*)(sw + S_OFFB);
            for (int i = tid; i < 64 * 128; i += 256) {
                int cl = i >> 7, p = i & 127;
                float2 s = g_scratch[((size_t)(b * CDIM + half * 64 + cl) << 14) + p0 + p];
                int off = p * 72 + cl;
                __nv_bfloat16 h;
                h = __float2bfloat16(s.x);
                sb[off]                = h;                                    // Sr_h
                sb[9216 + off]         = __float2bfloat16(s.x - __bfloat162float(h)); // Sr_l
                h = __float2bfloat16(s.y);
                sb[2 * 9216 + off]     = h;                                    // Si_h
                sb[3 * 9216 + off]     = __float2bfloat16(s.y - __bfloat162float(h)); // Si_l
            }
        }
        __syncthreads();

#pragma unroll
        for (int ks = 0; ks < 4; ++ks) {
            uint32_t af[4][4];
#pragma unroll
            for (int pl2 = 0; pl2 < 4; ++pl2) {
                const uint32_t* ap = sw + pl2 * PLANE32;
                int i0 = (m0 + g) * WSTR + ks * 8 + t;
                int i1 = i0 + 8 * WSTR;
                af[pl2][0] = ap[i0];     af[pl2][1] = ap[i1];
                af[pl2][2] = ap[i0 + 4]; af[pl2][3] = ap[i1 + 4];
            }
#pragma unroll
            for (int n = 0; n < 16; ++n) {
                uint32_t bf[4][2];
#pragma unroll
                for (int q = 0; q < 4; ++q) {
                    const uint32_t* bp = sw + S_OFFB + q * PLANE32;
                    int i0 = (n * 8 + g) * WSTR + ks * 8 + t;
                    bf[q][0] = bp[i0]; bf[q][1] = bp[i0 + 4];
                }
                MMA16816(acc[n], af[0], bf[0]);   // Wrh*Srh
                MMA16816(acc[n], af[1], bf[0]);   // Wrl*Srh
                MMA16816(acc[n], af[0], bf[1]);   // Wrh*Srl
                MMA16816(acc[n], af[2], bf[2]);   // -Wih*Sih
                MMA16816(acc[n], af[3], bf[2]);   // -Wil*Sih
                MMA16816(acc[n], af[2], bf[3]);   // -Wih*Sil
            }
        }
        __syncthreads();
    }

    // ---- epilogue: direct STG.64 ----
#pragma unroll
    for (int n = 0; n < 16; ++n) {
        int p = p0 + n * 8 + 2 * t;
        size_t r0 = ((size_t)(b * CDIM + m0 + g) << 14) + p;
        size_t r1 = ((size_t)(b * CDIM + m0 + g + 8) << 14) + p;
        *(float2*)(out + r0) = make_float2(acc[n][0], acc[n][1]);
        *(float2*)(out + r1) = make_float2(acc[n][2], acc[n][3]);
    }
}

// ---------------------------------------------------------------------------
// Kernel 3 (mode 0, complex output): FMA2 mix (known-correct fallback).
// ---------------------------------------------------------------------------
__global__ __launch_bounds__(256) void mix_kernel(const float* __restrict__ W_re,
                                                  const float* __restrict__ W_im,
                                                  float* __restrict__ out)
{
    extern __shared__ u64 sm64[];
    u64* Wrr = sm64;
    u64* Wii = sm64 + 2048;
    u64* Sr2 = sm64 + 4096;
    u64* Si2 = sm64 + 5120;
    u64* Sn2 = sm64 + 6144;

    const int bidx = blockIdx.x;
    const int b  = bidx >> 7;
    const int p0 = (bidx & 127) * 128;
    const int tid = threadIdx.x;
    const int tx = tid & 15;
    const int ty = tid >> 4;

    u64 accre[8][4], accim[8][4];
#pragma unroll
    for (int j = 0; j < 8; ++j)
#pragma unroll
        for (int m = 0; m < 4; ++m) { accre[j][m] = 0; accim[j][m] = 0; }

    for (int cc = 0; cc < CDIM; cc += 16) {
        __syncthreads();
        for (int idx = tid; idx < 2048; idx += 256) {
            int d = idx >> 4, ci = idx & 15;
            int gidx = d * CDIM + cc + ci;
            float wr = W_re[gidx], wi = W_im[gidx];
            Wrr[(d << 4) | ci] = pk2(wr, wr);
            Wii[(d << 4) | ci] = pk2(wi, wi);
        }
        for (int idx = tid; idx < 2048; idx += 256) {
            int ci = idx >> 7, p = idx & 127;
            float2 s = g_scratch[((size_t)(b * CDIM + cc + ci) << 14) + p0 + p];
            int e = p & 63, hi = p >> 6;
            ((float*)&Sr2[(ci << 6) + e])[hi] = s.x;
            ((float*)&Si2[(ci << 6) + e])[hi] = s.y;
            ((float*)&Sn2[(ci << 6) + e])[hi] = -s.y;
        }
        __syncthreads();
#pragma unroll
        for (int ci = 0; ci < 16; ++ci) {
            u64 sr[4], si[4], sn[4];
#pragma unroll
            for (int m = 0; m < 4; ++m) {
                int e = tx + 16 * m;
                sr[m] = Sr2[(ci << 6) + e];
                si[m] = Si2[(ci << 6) + e];
                sn[m] = Sn2[(ci << 6) + e];
            }
#pragma unroll
            for (int j = 0; j < 8; ++j) {
                u64 wr2 = Wrr[((ty + 16 * j) << 4) | ci];
                u64 wi2 = Wii[((ty + 16 * j) << 4) | ci];
#pragma unroll
                for (int m = 0; m < 4; ++m) {
                    FMA2(accre[j][m], wr2, sr[m]);
                    FMA2(accre[j][m], wi2, sn[m]);
                    FMA2(accim[j][m], wr2, si[m]);
                    FMA2(accim[j][m], wi2, sr[m]);
                }
            }
        }
    }

    float2* out2 = (float2*)out;
#pragma unroll
    for (int j = 0; j < 8; ++j) {
        int d = ty + 16 * j;
        size_t rowb = ((size_t)(b * CDIM + d) << 14) + p0;
#pragma unroll
        for (int m = 0; m < 4; ++m) {
            float reA, reB, imA, imB;
            upk2(accre[j][m], reA, reB);
            upk2(accim[j][m], imA, imB);
            out2[rowb + tx + 16 * m]      = make_float2(reA, imA);
            out2[rowb + tx + 16 * m + 64] = make_float2(reB, imB);
        }
    }
}

// ---------------------------------------------------------------------------
extern "C" void kernel_launch(void* const* d_in, const int* in_sizes, int n_in,
                              void* d_out, int out_size)
{
    const float* big[2]   = {nullptr, nullptr};
    const float* mid[16];
    const float* a_imag_p = nullptr;
    const float* log_dt_p = nullptr;
    int nbig = 0, nmid = 0, a_pos = -1;

    for (int i = 0; i < n_in; ++i) {
        const float* p = (const float*)d_in[i];
        int sz = in_sizes[i];
        if (sz == BDIM * CDIM * LDIM * LDIM) { if (nbig < 2) big[nbig++] = p; }
        else if (sz == 2 * NST)              { a_imag_p = p; a_pos = i; }
        else if (sz == 2 * CDIM)             { log_dt_p = p; }
        else if (sz == CDIM * CDIM && nmid < 16) { mid[nmid++] = p; }
    }
    if (nbig != 2 || !a_imag_p || !log_dt_p || nmid < 7) return;

    const float *u_re = big[0], *u_im = big[1];
    const float *log_A_real, *Bp_re, *Bp_im, *Cp_re, *Cp_im, *W_re, *W_im;
    if (a_pos == 0) {
        Bp_im = mid[0]; Bp_re = mid[1]; Cp_im = mid[2]; Cp_re = mid[3];
        W_im  = mid[4]; W_re  = mid[5]; log_A_real = mid[6];
        u_im = big[0]; u_re = big[1];
    } else {
        log_A_real = mid[0]; Bp_re = mid[1]; Bp_im = mid[2];
        Cp_re = mid[3]; Cp_im = mid[4]; W_re = mid[5]; W_im = mid[6];
    }

    const int mode = (out_size >= 2 * BDIM * CDIM * LDIM * LDIM) ? 0 : 1;

    k_kernel<<<128, 256>>>(log_A_real, a_imag_p, Bp_re, Bp_im, Cp_re, Cp_im, log_dt_p);

    const int conv_smem = PLANE * (int)sizeof(float2);
    cudaFuncSetAttribute(conv_kernel, cudaFuncAttributeMaxDynamicSharedMemorySize, conv_smem);
    conv_kernel<<<BDIM * CDIM, 256, conv_smem>>>(u_re, u_im);

    if (mode == 1) {
        wprep_kernel<<<64, 256>>>(W_re, W_im);
        cudaFuncSetAttribute(mix_mma_kernel, cudaFuncAttributeMaxDynamicSharedMemorySize, MIXMMA_SMEM);
        mix_mma_kernel<<<BDIM * 128, 256, MIXMMA_SMEM>>>((float*)d_out);
    } else {
        const int mix_smem = 7168 * (int)sizeof(u64);
        cudaFuncSetAttribute(mix_kernel, cudaFuncAttributeMaxDynamicSharedMemorySize, mix_smem);
        mix_kernel<<<BDIM * 128, 256, mix_smem>>>(W_re, W_im, (float*)d_out);
    }
}